// round 1
// baseline (speedup 1.0000x reference)
#include <cuda_runtime.h>
#include <cuda_bf16.h>

#define Hh 128
#define Ww 128
#define TSTEPS 10
#define NCH 96
#define NEG_INF (-1e30f)

// Row-max over a float4 with left/right neighbors fetched via warp shuffle.
// Warp layout: blockDim.x == 32, each lane tx owns columns [4tx, 4tx+4).
__device__ __forceinline__ float4 rowmax4(float4 v, int tx) {
    const unsigned mask = 0xffffffffu;
    float left  = __shfl_up_sync(mask, v.w, 1);   // v.w of lane tx-1
    float right = __shfl_down_sync(mask, v.x, 1); // v.x of lane tx+1
    if (tx == 0)  left  = NEG_INF;
    if (tx == 31) right = NEG_INF;
    float4 rm;
    rm.x = fmaxf(fmaxf(left, v.x), v.y);
    rm.y = fmaxf(fmaxf(v.x,  v.y), v.z);
    rm.z = fmaxf(fmaxf(v.y,  v.z), v.w);
    rm.w = fmaxf(fmaxf(v.z,  v.w), right);
    return rm;
}

__device__ __forceinline__ float4 max3(float4 a, float4 b, float4 c) {
    float4 r;
    r.x = fmaxf(fmaxf(a.x, b.x), c.x);
    r.y = fmaxf(fmaxf(a.y, b.y), c.y);
    r.z = fmaxf(fmaxf(a.z, b.z), c.z);
    r.w = fmaxf(fmaxf(a.w, b.w), c.w);
    return r;
}

// One CTA per (batch, channel) image. All 10 timesteps run in a single
// in-place SMEM buffer (64KB). Each warp owns 16 rows; halo row-maxes are
// preloaded into registers before a barrier, then rows update top-to-bottom
// with a register sliding window (read row i+1 before writing row i).
extern "C" __global__ void __launch_bounds__(256, 3)
cpool_kernel(const float* __restrict__ x,
             const float* __restrict__ ps,
             float* __restrict__ out) {
    extern __shared__ float buf[];          // Hh*Ww floats = 64KB
    float4* B4 = (float4*)buf;              // 32 float4 per row

    const int img = blockIdx.x;             // b*96 + c
    const int c   = img % NCH;
    const float p = ps[c];

    const int tx  = threadIdx.x;            // 0..31 (column group)
    const int wy  = threadIdx.y;            // 0..7  (warp id / row group)
    const int tid = wy * 32 + tx;

    // ---- Load image (fully coalesced float4) ----
    const float4* X4 = (const float4*)(x + (size_t)img * Hh * Ww);
    #pragma unroll
    for (int i = tid; i < Hh * Ww / 4; i += 256)
        B4[i] = X4[i];
    __syncthreads();

    const int r0 = wy * 16;
    const float4 ninf = make_float4(NEG_INF, NEG_INF, NEG_INF, NEG_INF);

    for (int t = 0; t < TSTEPS; t++) {
        // Phase 1: preload halo row-maxes (rows r0-1 and r0+16) into registers.
        float4 rm_prev = (wy > 0) ? rowmax4(B4[(r0 - 1) * 32 + tx], tx) : ninf;
        float4 rm_last = (wy < 7) ? rowmax4(B4[(r0 + 16) * 32 + tx], tx) : ninf;
        __syncthreads();  // all halo reads complete before anyone writes

        // Phase 2: in-place update of own 16 rows, top to bottom.
        float4 a_cur  = B4[r0 * 32 + tx];
        float4 rm_cur = rowmax4(a_cur, tx);
        #pragma unroll
        for (int k = 0; k < 16; k++) {
            const int i = r0 + k;
            float4 a_next, rm_next;
            if (k < 15) {
                a_next  = B4[(i + 1) * 32 + tx];   // old value (not yet written)
                rm_next = rowmax4(a_next, tx);
            } else {
                a_next  = a_cur;                    // dead after loop
                rm_next = rm_last;
            }
            float4 m = max3(rm_prev, rm_cur, rm_next);
            float4 o;
            o.x = fmaf(p, m.x - a_cur.x, a_cur.x);
            o.y = fmaf(p, m.y - a_cur.y, a_cur.y);
            o.z = fmaf(p, m.z - a_cur.z, a_cur.z);
            o.w = fmaf(p, m.w - a_cur.w, a_cur.w);
            B4[i * 32 + tx] = o;
            rm_prev = rm_cur;
            rm_cur  = rm_next;
            a_cur   = a_next;
        }
        __syncthreads();  // step complete before next step's halo reads
    }

    // ---- 2x2 avgpool, stride 2 -> 64x64, vectorized (2 outputs / unit) ----
    float* o_img = out + (size_t)img * 64 * 64;
    #pragma unroll
    for (int u = tid; u < 64 * 32; u += 256) {
        const int oy = u >> 5;
        const int g  = u & 31;                   // float4 column group
        float4 a = B4[(2 * oy)     * 32 + g];
        float4 b = B4[(2 * oy + 1) * 32 + g];
        float2 r;
        r.x = 0.25f * ((a.x + a.y) + (b.x + b.y));
        r.y = 0.25f * ((a.z + a.w) + (b.z + b.w));
        *(float2*)(o_img + oy * 64 + 2 * g) = r;
    }
}

extern "C" void kernel_launch(void* const* d_in, const int* in_sizes, int n_in,
                              void* d_out, int out_size) {
    const float* x  = (const float*)d_in[0];
    const float* ps = (const float*)d_in[1];
    // Defensive: identify pool_strength by its size (96 elements).
    if (n_in >= 2 && in_sizes[0] == NCH) {
        const float* tmp = x; x = ps; ps = tmp;
    }

    const int smem = Hh * Ww * sizeof(float);  // 65536
    cudaFuncSetAttribute((const void*)cpool_kernel,
                         cudaFuncAttributeMaxDynamicSharedMemorySize, smem);

    dim3 grid(32 * NCH);     // 3072 images
    dim3 block(32, 8);       // warp = one full row of float4s
    cpool_kernel<<<grid, block, smem>>>(x, ps, (float*)d_out);
}

// round 2
// speedup vs baseline: 1.4139x; 1.4139x over previous
#include <cuda_runtime.h>
#include <cuda_bf16.h>

#define TSTEPS 10
#define NCH 96
#define NEG_INF (-1e30f)
#define NW 16            // warps per CTA
#define RPW 8            // rows per warp (NW*RPW = 128)

// Row-max over a float4 with left/right neighbors via warp shuffle.
// Warp = one full 128-wide row; lane tx owns columns [4tx, 4tx+4).
__device__ __forceinline__ float4 rowmax4(float4 v, int tx) {
    const unsigned mask = 0xffffffffu;
    float left  = __shfl_up_sync(mask, v.w, 1);   // lane tx-1's v.w
    float right = __shfl_down_sync(mask, v.x, 1); // lane tx+1's v.x
    if (tx == 0)  left  = NEG_INF;
    if (tx == 31) right = NEG_INF;
    float4 rm;
    rm.x = fmaxf(fmaxf(left, v.x), v.y);
    rm.y = fmaxf(fmaxf(v.x,  v.y), v.z);
    rm.z = fmaxf(fmaxf(v.y,  v.z), v.w);
    rm.w = fmaxf(fmaxf(v.z,  v.w), right);
    return rm;
}

// One CTA per (batch, channel) image. Each warp holds its 8 rows in
// registers for all 10 timesteps; only the two boundary row-maxes per warp
// go through SMEM each step (double-buffered -> 1 barrier per step).
extern "C" __global__ void __launch_bounds__(512, 2)
cpool_kernel(const float* __restrict__ x,
             const float* __restrict__ ps,
             float* __restrict__ out) {
    // halo[buf][warp][0]=rowmax(first row), [1]=rowmax(last row); 32KB static
    __shared__ float4 halo[2][NW][2][32];

    const int img = blockIdx.x;              // b*96 + c
    const float p = ps[img % NCH];

    const int tx = threadIdx.x;              // 0..31
    const int wy = threadIdx.y;              // 0..15
    const int r0 = wy * RPW;

    // ---- Load own 8 rows straight into registers (coalesced LDG.128) ----
    const float4* X4 = (const float4*)(x + (size_t)img * 128 * 128);
    float4 v[RPW];
    #pragma unroll
    for (int k = 0; k < RPW; k++)
        v[k] = X4[(r0 + k) * 32 + tx];

    const float4 ninf = make_float4(NEG_INF, NEG_INF, NEG_INF, NEG_INF);

    #pragma unroll 1
    for (int t = 0; t < TSTEPS; t++) {
        const int b = t & 1;

        // Phase 1: publish row-maxes of boundary rows (pre-update values).
        float4 rm_first = rowmax4(v[0], tx);
        float4 rm_last  = rowmax4(v[RPW - 1], tx);
        halo[b][wy][0][tx] = rm_first;
        halo[b][wy][1][tx] = rm_last;
        __syncthreads();

        // Phase 2: fetch neighbor halo row-maxes.
        float4 rm_prev  = (wy > 0)      ? halo[b][wy - 1][1][tx] : ninf;
        float4 rm_below = (wy < NW - 1) ? halo[b][wy + 1][0][tx] : ninf;

        // Phase 3: register sliding window over own rows (in-place update;
        // rm_* always reflect pre-update values of the neighbor rows).
        float4 rm_cur = rm_first;
        #pragma unroll
        for (int k = 0; k < RPW; k++) {
            float4 rm_next;
            if (k == RPW - 1)      rm_next = rm_below;
            else if (k == RPW - 2) rm_next = rm_last;      // reuse phase-1 value
            else                   rm_next = rowmax4(v[k + 1], tx);

            float mx = fmaxf(fmaxf(rm_prev.x, rm_cur.x), rm_next.x);
            float my = fmaxf(fmaxf(rm_prev.y, rm_cur.y), rm_next.y);
            float mz = fmaxf(fmaxf(rm_prev.z, rm_cur.z), rm_next.z);
            float mw = fmaxf(fmaxf(rm_prev.w, rm_cur.w), rm_next.w);
            v[k].x = fmaf(p, mx - v[k].x, v[k].x);
            v[k].y = fmaf(p, my - v[k].y, v[k].y);
            v[k].z = fmaf(p, mz - v[k].z, v[k].z);
            v[k].w = fmaf(p, mw - v[k].w, v[k].w);

            rm_prev = rm_cur;
            rm_cur  = rm_next;
        }
        // No second barrier: double-buffered halo; the next step writes the
        // other buffer, and the step-t barrier already orders t-1 reads
        // against t+1 writes.
    }

    // ---- 2x2 avgpool stride 2 straight from registers -> 64x64 ----
    float* o_img = out + (size_t)img * 64 * 64;
    #pragma unroll
    for (int oy = 0; oy < RPW / 2; oy++) {
        float4 a = v[2 * oy];
        float4 b = v[2 * oy + 1];
        float2 r;
        r.x = 0.25f * ((a.x + a.y) + (b.x + b.y));
        r.y = 0.25f * ((a.z + a.w) + (b.z + b.w));
        *(float2*)(o_img + (4 * wy + oy) * 64 + 2 * tx) = r;
    }
}

extern "C" void kernel_launch(void* const* d_in, const int* in_sizes, int n_in,
                              void* d_out, int out_size) {
    const float* x  = (const float*)d_in[0];
    const float* ps = (const float*)d_in[1];
    if (n_in >= 2 && in_sizes[0] == NCH) {   // defensive input-order check
        const float* tmp = x; x = ps; ps = tmp;
    }

    dim3 grid(32 * NCH);        // 3072 images
    dim3 block(32, NW);         // 512 threads, warp = one image row
    cpool_kernel<<<grid, block>>>(x, ps, (float*)d_out);
}

// round 3
// speedup vs baseline: 1.5278x; 1.0805x over previous
#include <cuda_runtime.h>
#include <cuda_bf16.h>

#define TSTEPS 10
#define NCH 96
#define NEG_INF (-1e30f)
#define NW 16            // warps per CTA
#define RPW 8            // rows per warp (NW*RPW = 128)

// Row-max over a float4, boundary handled by PREDICATED max (no SEL):
// 7 FMNMX (2 predicated) + 2 SHFL per call.
__device__ __forceinline__ float4 rowmax4(float4 v, int tx) {
    const unsigned mask = 0xffffffffu;
    float left  = __shfl_up_sync(mask, v.w, 1);   // garbage in lane 0 (unused there)
    float right = __shfl_down_sync(mask, v.x, 1); // garbage in lane 31
    float t01 = fmaxf(v.x, v.y);
    float t12 = fmaxf(v.y, v.z);
    float t23 = fmaxf(v.z, v.w);
    float4 rm;
    rm.x = t01;
    if (tx > 0)  rm.x = fmaxf(rm.x, left);   // @P FMNMX
    rm.y = fmaxf(t01, v.z);
    rm.z = fmaxf(t12, v.w);
    rm.w = t23;
    if (tx < 31) rm.w = fmaxf(rm.w, right);  // @P FMNMX
    (void)t12;
    return rm;
}

// v = v + p*(m - v), computed as fma2(p, m, fma2(-p, v, v)) on packed f32x2.
__device__ __forceinline__ void blend4(float4& v, float4 m,
                                       unsigned long long pp,
                                       unsigned long long np) {
    asm("{\n\t"
        ".reg .b64 vv, mm, cc;\n\t"
        "mov.b64 vv, {%0, %1};\n\t"
        "mov.b64 mm, {%4, %5};\n\t"
        "fma.rn.f32x2 cc, %8, vv, vv;\n\t"
        "fma.rn.f32x2 cc, %9, mm, cc;\n\t"
        "mov.b64 {%0, %1}, cc;\n\t"
        "mov.b64 vv, {%2, %3};\n\t"
        "mov.b64 mm, {%6, %7};\n\t"
        "fma.rn.f32x2 cc, %8, vv, vv;\n\t"
        "fma.rn.f32x2 cc, %9, mm, cc;\n\t"
        "mov.b64 {%2, %3}, cc;\n\t"
        "}"
        : "+f"(v.x), "+f"(v.y), "+f"(v.z), "+f"(v.w)
        : "f"(m.x), "f"(m.y), "f"(m.z), "f"(m.w),
          "l"(np), "l"(pp));
}

__device__ __forceinline__ unsigned long long pack2(float a, float b) {
    unsigned long long r;
    asm("mov.b64 %0, {%1, %2};" : "=l"(r) : "f"(a), "f"(b));
    return r;
}

// One CTA per (batch, channel) image. Each warp holds its 8 rows in
// registers for all 10 timesteps; only the two boundary row-maxes per warp
// go through SMEM each step (double-buffered -> 1 barrier per step).
extern "C" __global__ void __launch_bounds__(512, 2)
cpool_kernel(const float* __restrict__ x,
             const float* __restrict__ ps,
             float* __restrict__ out) {
    __shared__ float4 halo[2][NW][2][32];     // 32KB

    const int img = blockIdx.x;               // b*96 + c
    const float p = ps[img % NCH];
    const unsigned long long pp = pack2(p, p);
    const unsigned long long np = pack2(-p, -p);

    const int tx = threadIdx.x;               // 0..31
    const int wy = threadIdx.y;               // 0..15
    const int r0 = wy * RPW;

    // ---- Load own 8 rows straight into registers (coalesced LDG.128) ----
    const float4* X4 = (const float4*)(x + (size_t)img * 128 * 128);
    float4 v[RPW];
    #pragma unroll
    for (int k = 0; k < RPW; k++)
        v[k] = X4[(r0 + k) * 32 + tx];

    const float4 ninf = make_float4(NEG_INF, NEG_INF, NEG_INF, NEG_INF);

    #pragma unroll 1
    for (int t = 0; t < TSTEPS; t++) {
        const int b = t & 1;

        // Phase 1: publish pre-update row-maxes of boundary rows.
        float4 rm_first = rowmax4(v[0], tx);
        float4 rm_last  = rowmax4(v[RPW - 1], tx);
        halo[b][wy][0][tx] = rm_first;
        halo[b][wy][1][tx] = rm_last;
        __syncthreads();

        // Phase 2: fetch neighbor halo row-maxes.
        float4 rm_prev  = (wy > 0)      ? halo[b][wy - 1][1][tx] : ninf;
        float4 rm_below = (wy < NW - 1) ? halo[b][wy + 1][0][tx] : ninf;

        // Phase 3: register sliding window, in-place (rm_* are pre-update).
        float4 rm_cur = rm_first;
        #pragma unroll
        for (int k = 0; k < RPW; k++) {
            float4 rm_next;
            if (k == RPW - 1)      rm_next = rm_below;
            else if (k == RPW - 2) rm_next = rm_last;
            else                   rm_next = rowmax4(v[k + 1], tx);

            float4 m;
            m.x = fmaxf(fmaxf(rm_prev.x, rm_cur.x), rm_next.x);
            m.y = fmaxf(fmaxf(rm_prev.y, rm_cur.y), rm_next.y);
            m.z = fmaxf(fmaxf(rm_prev.z, rm_cur.z), rm_next.z);
            m.w = fmaxf(fmaxf(rm_prev.w, rm_cur.w), rm_next.w);
            blend4(v[k], m, pp, np);

            rm_prev = rm_cur;
            rm_cur  = rm_next;
        }
        // Double-buffered halo: no second barrier needed.
    }

    // ---- 2x2 avgpool stride 2 straight from registers -> 64x64 ----
    float* o_img = out + (size_t)img * 64 * 64;
    #pragma unroll
    for (int oy = 0; oy < RPW / 2; oy++) {
        float4 a = v[2 * oy];
        float4 b = v[2 * oy + 1];
        float2 r;
        r.x = 0.25f * ((a.x + a.y) + (b.x + b.y));
        r.y = 0.25f * ((a.z + a.w) + (b.z + b.w));
        *(float2*)(o_img + (4 * wy + oy) * 64 + 2 * tx) = r;
    }
}

extern "C" void kernel_launch(void* const* d_in, const int* in_sizes, int n_in,
                              void* d_out, int out_size) {
    const float* x  = (const float*)d_in[0];
    const float* ps = (const float*)d_in[1];
    if (n_in >= 2 && in_sizes[0] == NCH) {   // defensive input-order check
        const float* tmp = x; x = ps; ps = tmp;
    }

    dim3 grid(32 * NCH);        // 3072 images
    dim3 block(32, NW);         // 512 threads, warp = one image row
    cpool_kernel<<<grid, block>>>(x, ps, (float*)d_out);
}